// round 3
// baseline (speedup 1.0000x reference)
#include <cuda_runtime.h>
#include <math.h>

#define NB 64
#define TT 1024
#define DD 512
#define HH 512
#define FH 2048   // 4*H
#define GRID_R 128  // recurrence blocks (<=148 SMs, 1/SM => all co-resident)

// Scratch: xw = x@Wx + b  [N*T, 4H]  (512 MB) and grid-barrier counter.
__device__ float g_xw[(size_t)NB * TT * FH];
__device__ unsigned g_bar;

__global__ void reset_bar_kernel() { g_bar = 0u; }

// ---------------------------------------------------------------------------
// Phase 1: xw[r, j] = sum_k x[r, k] * Wx[k, j] + b[j],  r = n*T + t
// Classic fp32 SGEMM: BM=128, BN=128, BK=8, 256 threads, 8x8 per thread.
// ---------------------------------------------------------------------------
__global__ __launch_bounds__(256) void sgemm_xw_kernel(
    const float* __restrict__ A,      // x    [65536, 512]
    const float* __restrict__ B,      // Wx   [512, 2048]
    const float* __restrict__ bias)   // b    [2048]
{
    __shared__ float As[8][128];
    __shared__ float Bs[8][128];

    const int tid = threadIdx.x;
    const int bx = blockIdx.x;    // col block (0..15)
    const int by = blockIdx.y;    // row block (0..511)
    const int tx = tid & 15;
    const int ty = tid >> 4;

    const float* Ab = A + (size_t)by * 128 * DD;
    const float* Bb = B + bx * 128;

    float acc[8][8];
    #pragma unroll
    for (int i = 0; i < 8; ++i)
        #pragma unroll
        for (int j = 0; j < 8; ++j)
            acc[i][j] = 0.f;

    const int arow = tid >> 1;          // 0..127
    const int ac4  = (tid & 1) * 4;     // 0 or 4
    const int brow = tid >> 5;          // 0..7
    const int bc4  = (tid & 31) * 4;    // 0..124

    for (int kc = 0; kc < DD; kc += 8) {
        float4 av = *(const float4*)(Ab + (size_t)arow * DD + kc + ac4);
        float4 bv = *(const float4*)(Bb + (size_t)(kc + brow) * FH + bc4);
        As[ac4 + 0][arow] = av.x;
        As[ac4 + 1][arow] = av.y;
        As[ac4 + 2][arow] = av.z;
        As[ac4 + 3][arow] = av.w;
        *(float4*)&Bs[brow][bc4] = bv;
        __syncthreads();

        #pragma unroll
        for (int k = 0; k < 8; ++k) {
            float4 a0 = *(const float4*)&As[k][ty * 8];
            float4 a1 = *(const float4*)&As[k][ty * 8 + 4];
            float4 b0 = *(const float4*)&Bs[k][tx * 8];
            float4 b1 = *(const float4*)&Bs[k][tx * 8 + 4];
            float ra[8] = {a0.x, a0.y, a0.z, a0.w, a1.x, a1.y, a1.z, a1.w};
            float rb[8] = {b0.x, b0.y, b0.z, b0.w, b1.x, b1.y, b1.z, b1.w};
            #pragma unroll
            for (int i = 0; i < 8; ++i)
                #pragma unroll
                for (int j = 0; j < 8; ++j)
                    acc[i][j] = fmaf(ra[i], rb[j], acc[i][j]);
        }
        __syncthreads();
    }

    float* C = g_xw + (size_t)(by * 128) * FH + bx * 128;
    float bb[8];
    #pragma unroll
    for (int j = 0; j < 8; ++j)
        bb[j] = bias[bx * 128 + tx * 8 + j];

    #pragma unroll
    for (int i = 0; i < 8; ++i) {
        int r = ty * 8 + i;
        float4 v0, v1;
        v0.x = acc[i][0] + bb[0]; v0.y = acc[i][1] + bb[1];
        v0.z = acc[i][2] + bb[2]; v0.w = acc[i][3] + bb[3];
        v1.x = acc[i][4] + bb[4]; v1.y = acc[i][5] + bb[5];
        v1.z = acc[i][6] + bb[6]; v1.w = acc[i][7] + bb[7];
        *(float4*)(C + (size_t)r * FH + tx * 8)     = v0;
        *(float4*)(C + (size_t)r * FH + tx * 8 + 4) = v1;
    }
}

// ---------------------------------------------------------------------------
// Phase 2: ONE persistent kernel, software grid barrier between timesteps.
// 128 blocks (1/SM, co-resident). Block b owns hidden units m0=b*4..b*4+3,
// i.e. gate columns g*512 + m0 + u, g in 0..3, u in 0..3 (16 columns).
// Wh slice [512 x 16] lives in smem for the whole kernel (loaded once).
// Per step: stage h [64 x 512] transposed into smem, 8-warp split-K GEMM,
// smem reduction, gates; c stays in a register (fixed thread->(n,u) map).
// Dynamic smem: Whs 32KB + Hs 128KB + Ap 32KB = 192KB  (1 block/SM).
// ---------------------------------------------------------------------------
__global__ __launch_bounds__(256) void lstm_persist_kernel(
    const float* __restrict__ Wh,     // [512, 2048]
    const float* __restrict__ h0,     // [64, 512]
    float* __restrict__ out)          // [64, 1024, 512]
{
    extern __shared__ float smem[];
    float* Whs = smem;                          // [512][16]
    float* Hs  = smem + 512 * 16;               // [512][64]
    float* Ap  = smem + 512 * 16 + 512 * 64;    // [8][16][64]

    const int tid  = threadIdx.x;
    const int w    = tid >> 5;
    const int lane = tid & 31;
    const int ln   = lane >> 2;   // 0..7  -> n group (8 rows)
    const int lc   = lane & 3;    // 0..3  -> c group (4 cols)
    const int m0   = blockIdx.x * 4;

    // Load Wh slice once: Whs[k][c], c = g*4+u -> global col g*512 + m0 + u
    {
        const int wc  = tid & 15;       // c
        const int wk0 = tid >> 4;       // 0..15
        const int wcol = (wc >> 2) * HH + m0 + (wc & 3);
        #pragma unroll 4
        for (int j = 0; j < 32; ++j) {
            int k = wk0 + 16 * j;
            Whs[k * 16 + wc] = Wh[(size_t)k * FH + wcol];
        }
    }

    // Epilogue thread mapping (fixed across steps): thread -> (n, u)
    const int en = tid >> 2;      // batch 0..63
    const int eu = tid & 3;       // unit  0..3
    float creg = 0.f;             // cell state, register-resident

    const int hn = tid & 63;      // batch row this thread stages
    const int hq = tid >> 6;      // 0..3

    for (int t = 0; t < TT; ++t) {
        // Prefetch xw for this step (independent of h; DRAM latency hidden)
        float xwv[4];
        #pragma unroll
        for (int g = 0; g < 4; ++g)
            xwv[g] = g_xw[(size_t)(en * TT + t) * FH + g * HH + m0 + eu];

        const float* hp;
        long hstr;
        if (t == 0) { hp = h0;                          hstr = HH; }
        else        { hp = out + (size_t)(t - 1) * HH;  hstr = (long)TT * HH; }

        if (t > 0) {
            // Release: all threads fence their h stores, then one arrival.
            __threadfence();
            __syncthreads();
            if (tid == 0) {
                atomicAdd(&g_bar, 1u);
                const unsigned target = (unsigned)t * GRID_R;
                while (*((volatile unsigned*)&g_bar) < target) { }
                __threadfence();  // acquire
            }
            __syncthreads();
        }

        // Stage h_{t-1} -> Hs transposed [k][n]  (L2 loads: dodge stale L1)
        {
            const float* hrow = hp + (size_t)hn * hstr;
            #pragma unroll 8
            for (int j = 0; j < 32; ++j) {
                int q = hq + 4 * j;                 // float4 index 0..127
                float4 v = __ldcg((const float4*)hrow + q);
                Hs[(q * 4 + 0) * 64 + hn] = v.x;
                Hs[(q * 4 + 1) * 64 + hn] = v.y;
                Hs[(q * 4 + 2) * 64 + hn] = v.z;
                Hs[(q * 4 + 3) * 64 + hn] = v.w;
            }
        }
        __syncthreads();

        // Split-K: warp w handles k in [w*64, w*64+64). Lane tile 8n x 4c.
        float acc[8][4];
        #pragma unroll
        for (int i = 0; i < 8; ++i)
            #pragma unroll
            for (int j = 0; j < 4; ++j)
                acc[i][j] = 0.f;

        #pragma unroll 8
        for (int kk = 0; kk < 64; ++kk) {
            int k = w * 64 + kk;
            float4 ha = *(const float4*)&Hs[k * 64 + ln * 8];
            float4 hb = *(const float4*)&Hs[k * 64 + ln * 8 + 4];
            float4 wv = *(const float4*)&Whs[k * 16 + lc * 4];
            float hv[8] = {ha.x, ha.y, ha.z, ha.w, hb.x, hb.y, hb.z, hb.w};
            float wf[4] = {wv.x, wv.y, wv.z, wv.w};
            #pragma unroll
            for (int i = 0; i < 8; ++i)
                #pragma unroll
                for (int j = 0; j < 4; ++j)
                    acc[i][j] = fmaf(hv[i], wf[j], acc[i][j]);
        }

        // Reduce across warps via smem
        #pragma unroll
        for (int i = 0; i < 8; ++i)
            #pragma unroll
            for (int j = 0; j < 4; ++j)
                Ap[(w * 16 + lc * 4 + j) * 64 + ln * 8 + i] = acc[i][j];
        __syncthreads();

        float a[4];
        #pragma unroll
        for (int g = 0; g < 4; ++g) {
            float s = xwv[g];
            #pragma unroll
            for (int ww = 0; ww < 8; ++ww)
                s += Ap[(ww * 16 + g * 4 + eu) * 64 + en];
            a[g] = s;
        }
        float ig = 1.f / (1.f + __expf(-a[0]));
        float fg = 1.f / (1.f + __expf(-a[1]));
        float og = 1.f / (1.f + __expf(-a[2]));
        float gg = tanhf(a[3]);
        creg = fmaf(fg, creg, ig * gg);
        float hval = og * tanhf(creg);
        out[(size_t)en * TT * HH + (size_t)t * HH + m0 + eu] = hval;

        __syncthreads();   // Ap / Hs reuse safety before next iteration
    }
}

// ---------------------------------------------------------------------------
extern "C" void kernel_launch(void* const* d_in, const int* in_sizes, int n_in,
                              void* d_out, int out_size)
{
    const float* x  = (const float*)d_in[0];   // [64, 1024, 512]
    const float* h0 = (const float*)d_in[1];   // [64, 512]
    const float* Wx = (const float*)d_in[2];   // [512, 2048]
    const float* Wh = (const float*)d_in[3];   // [512, 2048]
    const float* b  = (const float*)d_in[4];   // [2048]
    float* out = (float*)d_out;                // [64, 1024, 512]

    const int smem_bytes = (512 * 16 + 512 * 64 + 8 * 16 * 64) * 4;  // 192 KB
    cudaFuncSetAttribute(lstm_persist_kernel,
                         cudaFuncAttributeMaxDynamicSharedMemorySize, smem_bytes);

    reset_bar_kernel<<<1, 1>>>();

    dim3 g1(FH / 128, (NB * TT) / 128);        // (16, 512)
    sgemm_xw_kernel<<<g1, 256>>>(x, Wx, b);

    lstm_persist_kernel<<<GRID_R, 256, smem_bytes>>>(Wh, h0, out);
}

// round 5
// speedup vs baseline: 1.2540x; 1.2540x over previous
#include <cuda_runtime.h>
#include <math.h>

#define NB 64
#define TT 1024
#define DD 512
#define HH 512
#define FH 2048   // 4*H
#define GRID_R 128  // recurrence blocks (1/SM, all co-resident)

// Scratch: xw = x@Wx + b [N*T, 4H] (512 MB), ping-pong h, barrier counter.
__device__ float g_xw[(size_t)NB * TT * FH];
__device__ float g_h[2][NB * HH];
__device__ unsigned g_bar;

union F2 { float2 f; unsigned long long u; };

#define FMA2(d, a, b) \
    asm("fma.rn.f32x2 %0, %1, %2, %3;" : "=l"((d).u) : "l"((a).u), "l"((b).u), "l"((d).u))

// ---------------------------------------------------------------------------
// Phase 1: xw[r, j] = sum_k x[r, k] * Wx[k, j] + b[j],  r = n*T + t
// fp32 SGEMM with packed f32x2 FMA: BM=128, BN=128, BK=8, 256 thr, 8x8/thr.
// B tile stored DUPLICATED in smem so the f32x2 "b" operand needs no packing.
// ---------------------------------------------------------------------------
__global__ __launch_bounds__(256) void sgemm_xw_kernel(
    const float* __restrict__ A,      // x    [65536, 512]
    const float* __restrict__ B,      // Wx   [512, 2048]
    const float* __restrict__ bias)   // b    [2048]
{
    __shared__ float As[8][128];
    __shared__ float Bs2[8][256];     // duplicated pairs (v, v)

    const int tid = threadIdx.x;
    const int bx = blockIdx.x;    // col block (0..15)
    const int by = blockIdx.y;    // row block (0..511)
    const int tx = tid & 15;
    const int ty = tid >> 4;

    if (bx == 0 && by == 0 && tid == 0) g_bar = 0u;   // barrier reset for phase 2

    const float* Ab = A + (size_t)by * 128 * DD;
    const float* Bb = B + bx * 128;

    F2 acc[4][8];                 // [row-pair][col]
    #pragma unroll
    for (int i = 0; i < 4; ++i)
        #pragma unroll
        for (int j = 0; j < 8; ++j)
            acc[i][j].u = 0ull;

    const int arow = tid >> 1;          // 0..127
    const int ac4  = (tid & 1) * 4;     // 0 or 4
    const int brow = tid >> 5;          // 0..7
    const int bc4  = (tid & 31) * 4;    // 0..124

    for (int kc = 0; kc < DD; kc += 8) {
        float4 av = *(const float4*)(Ab + (size_t)arow * DD + kc + ac4);
        float4 bv = *(const float4*)(Bb + (size_t)(kc + brow) * FH + bc4);
        As[ac4 + 0][arow] = av.x;
        As[ac4 + 1][arow] = av.y;
        As[ac4 + 2][arow] = av.z;
        As[ac4 + 3][arow] = av.w;
        *(float2*)&Bs2[brow][2 * (bc4 + 0)] = make_float2(bv.x, bv.x);
        *(float2*)&Bs2[brow][2 * (bc4 + 1)] = make_float2(bv.y, bv.y);
        *(float2*)&Bs2[brow][2 * (bc4 + 2)] = make_float2(bv.z, bv.z);
        *(float2*)&Bs2[brow][2 * (bc4 + 3)] = make_float2(bv.w, bv.w);
        __syncthreads();

        #pragma unroll
        for (int k = 0; k < 8; ++k) {
            float4 a0 = *(const float4*)&As[k][ty * 8];
            float4 a1 = *(const float4*)&As[k][ty * 8 + 4];
            F2 ra[4];
            ra[0].f = make_float2(a0.x, a0.y);
            ra[1].f = make_float2(a0.z, a0.w);
            ra[2].f = make_float2(a1.x, a1.y);
            ra[3].f = make_float2(a1.z, a1.w);
            #pragma unroll
            for (int j = 0; j < 8; ++j) {
                F2 rb = *(F2*)&Bs2[k][2 * (tx * 8 + j)];
                #pragma unroll
                for (int i = 0; i < 4; ++i)
                    FMA2(acc[i][j], ra[i], rb);
            }
        }
        __syncthreads();
    }

    float* C = g_xw + (size_t)(by * 128) * FH + bx * 128;
    float bb[8];
    #pragma unroll
    for (int j = 0; j < 8; ++j)
        bb[j] = bias[bx * 128 + tx * 8 + j];

    #pragma unroll
    for (int i = 0; i < 4; ++i) {
        #pragma unroll
        for (int half = 0; half < 2; ++half) {
            int r = ty * 8 + i * 2 + half;
            float4 v0, v1;
            v0.x = (half ? acc[i][0].f.y : acc[i][0].f.x) + bb[0];
            v0.y = (half ? acc[i][1].f.y : acc[i][1].f.x) + bb[1];
            v0.z = (half ? acc[i][2].f.y : acc[i][2].f.x) + bb[2];
            v0.w = (half ? acc[i][3].f.y : acc[i][3].f.x) + bb[3];
            v1.x = (half ? acc[i][4].f.y : acc[i][4].f.x) + bb[4];
            v1.y = (half ? acc[i][5].f.y : acc[i][5].f.x) + bb[5];
            v1.z = (half ? acc[i][6].f.y : acc[i][6].f.x) + bb[6];
            v1.w = (half ? acc[i][7].f.y : acc[i][7].f.x) + bb[7];
            *(float4*)(C + (size_t)r * FH + tx * 8)     = v0;
            *(float4*)(C + (size_t)r * FH + tx * 8 + 4) = v1;
        }
    }
}

// ---------------------------------------------------------------------------
// Phase 2: ONE persistent kernel, software grid barrier between timesteps.
// 128 blocks. Block b owns hidden units m0=b*4..b*4+3 -> 16 gate columns.
// Wh slice [512 x 16] lives in smem DUPLICATED as (v,v) pairs (64 KB).
// Per step: stage h [64 x 512] transposed into smem (from compact ping-pong
// buffer), 8-warp split-K f32x2 GEMM, smem reduction, gates; c in register.
// Dyn smem: Whs2 64KB + Hs 128KB + Ap 33KB = 230400 B (1 block/SM).
// ---------------------------------------------------------------------------
__global__ __launch_bounds__(256) void lstm_persist_kernel(
    const float* __restrict__ Wh,     // [512, 2048]
    const float* __restrict__ h0,     // [64, 512]
    float* __restrict__ out)          // [64, 1024, 512]
{
    extern __shared__ char sm_raw[];
    float2* Whs2 = (float2*)sm_raw;                       // [512*16] pairs
    float*  Hs   = (float*)(sm_raw + 65536);              // [512][64]
    float*  Ap   = (float*)(sm_raw + 65536 + 131072);     // [128][66]

    const int tid  = threadIdx.x;
    const int w    = tid >> 5;
    const int lane = tid & 31;
    const int ln   = lane >> 2;   // 0..7  -> n group (8 batches)
    const int lc   = lane & 3;    // 0..3  -> c group (4 cols)
    const int m0   = blockIdx.x * 4;

    // Load Wh slice once, duplicated: col c = g*4+u -> global g*512 + m0 + u
    {
        const int wc  = tid & 15;
        const int wk0 = tid >> 4;       // 0..15
        const int wcol = (wc >> 2) * HH + m0 + (wc & 3);
        #pragma unroll 4
        for (int j = 0; j < 32; ++j) {
            int k = wk0 + 16 * j;
            float v = Wh[(size_t)k * FH + wcol];
            Whs2[k * 16 + wc] = make_float2(v, v);
        }
    }

    const int en = tid >> 2;      // epilogue batch 0..63
    const int eu = tid & 3;       // epilogue unit  0..3
    float creg = 0.f;

    const int hn = tid & 63;      // staging batch row
    const int hq = tid >> 6;      // 0..3

    for (int t = 0; t < TT; ++t) {
        // Prefetch xw for this step (independent of the barrier)
        float xwv[4];
        #pragma unroll
        for (int g = 0; g < 4; ++g)
            xwv[g] = g_xw[(size_t)(en * TT + t) * FH + g * HH + m0 + eu];

        const float* hp = (t == 0) ? h0 : g_h[(t - 1) & 1];

        if (t > 0) {
            __threadfence();          // release own h stores
            __syncthreads();
            if (tid == 0) {
                atomicAdd(&g_bar, 1u);
                const unsigned target = (unsigned)t * GRID_R;
                while (*((volatile unsigned*)&g_bar) < target) { }
                __threadfence();      // acquire
            }
            __syncthreads();          // also orders Hs/Ap reuse across steps
        }

        // Stage h_{t-1} -> Hs transposed [k][n] (L2 loads, compact buffer)
        {
            const float4* hrow = (const float4*)(hp + (size_t)hn * HH);
            #pragma unroll 8
            for (int j = 0; j < 32; ++j) {
                int q = hq + 4 * j;                 // float4 index 0..127
                float4 v = __ldcg(hrow + q);
                Hs[(q * 4 + 0) * 64 + hn] = v.x;
                Hs[(q * 4 + 1) * 64 + hn] = v.y;
                Hs[(q * 4 + 2) * 64 + hn] = v.z;
                Hs[(q * 4 + 3) * 64 + hn] = v.w;
            }
        }
        __syncthreads();

        // Split-K: warp w owns k in [w*64, w*64+64). Lane tile 8n x 4c,
        // n packed in f32x2 pairs (4 pairs), Wh operand pre-duplicated.
        F2 acc[4][4];
        #pragma unroll
        for (int p = 0; p < 4; ++p)
            #pragma unroll
            for (int j = 0; j < 4; ++j)
                acc[p][j].u = 0ull;

        #pragma unroll 4
        for (int kk = 0; kk < 64; ++kk) {
            int k = w * 64 + kk;
            float4 ha = *(const float4*)&Hs[k * 64 + ln * 8];
            float4 hb = *(const float4*)&Hs[k * 64 + ln * 8 + 4];
            F2 hv[4];
            hv[0].f = make_float2(ha.x, ha.y);
            hv[1].f = make_float2(ha.z, ha.w);
            hv[2].f = make_float2(hb.x, hb.y);
            hv[3].f = make_float2(hb.z, hb.w);
            #pragma unroll
            for (int j = 0; j < 4; ++j) {
                F2 wv = *(F2*)&Whs2[k * 16 + lc * 4 + j];
                #pragma unroll
                for (int p = 0; p < 4; ++p)
                    FMA2(acc[p][j], hv[p], wv);
            }
        }

        // Cross-warp reduce via padded smem (stride 66, float2 stores)
        #pragma unroll
        for (int p = 0; p < 4; ++p)
            #pragma unroll
            for (int j = 0; j < 4; ++j)
                *(float2*)&Ap[(w * 16 + lc * 4 + j) * 66 + ln * 8 + 2 * p] =
                    acc[p][j].f;
        __syncthreads();

        float a[4];
        #pragma unroll
        for (int g = 0; g < 4; ++g) {
            float s = xwv[g];
            #pragma unroll
            for (int ww = 0; ww < 8; ++ww)
                s += Ap[(ww * 16 + g * 4 + eu) * 66 + en];
            a[g] = s;
        }
        float ig = 1.f / (1.f + __expf(-a[0]));
        float fg = 1.f / (1.f + __expf(-a[1]));
        float og = 1.f / (1.f + __expf(-a[2]));
        float gg = tanhf(a[3]);
        creg = fmaf(fg, creg, ig * gg);
        float hval = og * tanhf(creg);
        out[(size_t)en * TT * HH + (size_t)t * HH + m0 + eu] = hval;
        g_h[t & 1][en * HH + m0 + eu] = hval;
    }
}

// ---------------------------------------------------------------------------
extern "C" void kernel_launch(void* const* d_in, const int* in_sizes, int n_in,
                              void* d_out, int out_size)
{
    const float* x  = (const float*)d_in[0];   // [64, 1024, 512]
    const float* h0 = (const float*)d_in[1];   // [64, 512]
    const float* Wx = (const float*)d_in[2];   // [512, 2048]
    const float* Wh = (const float*)d_in[3];   // [512, 2048]
    const float* b  = (const float*)d_in[4];   // [2048]
    float* out = (float*)d_out;                // [64, 1024, 512]

    const int smem_bytes = 65536 + 131072 + 128 * 66 * 4;  // 230400 B
    cudaFuncSetAttribute(lstm_persist_kernel,
                         cudaFuncAttributeMaxDynamicSharedMemorySize, smem_bytes);

    dim3 g1(FH / 128, (NB * TT) / 128);        // (16, 512)
    sgemm_xw_kernel<<<g1, 256>>>(x, Wx, b);

    lstm_persist_kernel<<<GRID_R, 256, smem_bytes>>>(Wh, h0, out);
}

// round 6
// speedup vs baseline: 1.6408x; 1.3085x over previous
#include <cuda_runtime.h>
#include <math.h>

#define NB 64
#define TT 1024
#define DD 512
#define HH 512
#define FH 2048    // 4*H
#define GRID_R 128 // recurrence blocks (1/SM, all co-resident)
#define NTHR 512   // threads per recurrence block (16 warps)

// Scratch: xw in [T, N, 4H] layout (512 MB), ping-pong h, barrier counter.
__device__ float g_xw[(size_t)NB * TT * FH];
__device__ float g_h[2][NB * HH];
__device__ unsigned g_bar;

union F2 { float2 f; unsigned long long u; };

#define FMA2(d, a, b) \
    asm("fma.rn.f32x2 %0, %1, %2, %3;" : "=l"((d).u) : "l"((a).u), "l"((b).u), "l"((d).u))

__device__ __forceinline__ float tanh_fast(float x) {
    float y;
    asm("tanh.approx.f32 %0, %1;" : "=f"(y) : "f"(x));
    return y;
}
__device__ __forceinline__ float sigmoid_fast(float x) {
    return fmaf(tanh_fast(0.5f * x), 0.5f, 0.5f);
}

// ---------------------------------------------------------------------------
// Phase 1: xw[t*64+n, j] = sum_k x[n*1024+t, k] * Wx[k, j] + b[j]
// fp32 SGEMM with packed f32x2 FMA: BM=128, BN=128, BK=8, 256 thr, 8x8/thr.
// B tile stored DUPLICATED in smem so the f32x2 "b" operand needs no packing.
// Output rows are written TRANSPOSED to [T, N] order for phase-2 locality.
// ---------------------------------------------------------------------------
__global__ __launch_bounds__(256) void sgemm_xw_kernel(
    const float* __restrict__ A,      // x    [65536, 512]
    const float* __restrict__ B,      // Wx   [512, 2048]
    const float* __restrict__ bias)   // b    [2048]
{
    __shared__ float As[8][128];
    __shared__ float Bs2[8][256];     // duplicated pairs (v, v)

    const int tid = threadIdx.x;
    const int bx = blockIdx.x;    // col block (0..15)
    const int by = blockIdx.y;    // row block (0..511)
    const int tx = tid & 15;
    const int ty = tid >> 4;

    if (bx == 0 && by == 0 && tid == 0) g_bar = 0u;   // barrier reset for phase 2

    const float* Ab = A + (size_t)by * 128 * DD;
    const float* Bb = B + bx * 128;

    F2 acc[4][8];                 // [row-pair][col]
    #pragma unroll
    for (int i = 0; i < 4; ++i)
        #pragma unroll
        for (int j = 0; j < 8; ++j)
            acc[i][j].u = 0ull;

    const int arow = tid >> 1;          // 0..127
    const int ac4  = (tid & 1) * 4;     // 0 or 4
    const int brow = tid >> 5;          // 0..7
    const int bc4  = (tid & 31) * 4;    // 0..124

    for (int kc = 0; kc < DD; kc += 8) {
        float4 av = *(const float4*)(Ab + (size_t)arow * DD + kc + ac4);
        float4 bv = *(const float4*)(Bb + (size_t)(kc + brow) * FH + bc4);
        As[ac4 + 0][arow] = av.x;
        As[ac4 + 1][arow] = av.y;
        As[ac4 + 2][arow] = av.z;
        As[ac4 + 3][arow] = av.w;
        *(float2*)&Bs2[brow][2 * (bc4 + 0)] = make_float2(bv.x, bv.x);
        *(float2*)&Bs2[brow][2 * (bc4 + 1)] = make_float2(bv.y, bv.y);
        *(float2*)&Bs2[brow][2 * (bc4 + 2)] = make_float2(bv.z, bv.z);
        *(float2*)&Bs2[brow][2 * (bc4 + 3)] = make_float2(bv.w, bv.w);
        __syncthreads();

        #pragma unroll
        for (int k = 0; k < 8; ++k) {
            float4 a0 = *(const float4*)&As[k][ty * 8];
            float4 a1 = *(const float4*)&As[k][ty * 8 + 4];
            F2 ra[4];
            ra[0].f = make_float2(a0.x, a0.y);
            ra[1].f = make_float2(a0.z, a0.w);
            ra[2].f = make_float2(a1.x, a1.y);
            ra[3].f = make_float2(a1.z, a1.w);
            #pragma unroll
            for (int j = 0; j < 8; ++j) {
                F2 rb = *(F2*)&Bs2[k][2 * (tx * 8 + j)];
                #pragma unroll
                for (int i = 0; i < 4; ++i)
                    FMA2(acc[i][j], ra[i], rb);
            }
        }
        __syncthreads();
    }

    float bb[8];
    #pragma unroll
    for (int j = 0; j < 8; ++j)
        bb[j] = bias[bx * 128 + tx * 8 + j];

    #pragma unroll
    for (int i = 0; i < 4; ++i) {
        #pragma unroll
        for (int half = 0; half < 2; ++half) {
            int r = by * 128 + ty * 8 + i * 2 + half;   // global A row
            int n = r >> 10;                            // batch
            int t = r & 1023;                           // time
            float* C = g_xw + (size_t)(t * NB + n) * FH + bx * 128;
            float4 v0, v1;
            v0.x = (half ? acc[i][0].f.y : acc[i][0].f.x) + bb[0];
            v0.y = (half ? acc[i][1].f.y : acc[i][1].f.x) + bb[1];
            v0.z = (half ? acc[i][2].f.y : acc[i][2].f.x) + bb[2];
            v0.w = (half ? acc[i][3].f.y : acc[i][3].f.x) + bb[3];
            v1.x = (half ? acc[i][4].f.y : acc[i][4].f.x) + bb[4];
            v1.y = (half ? acc[i][5].f.y : acc[i][5].f.x) + bb[5];
            v1.z = (half ? acc[i][6].f.y : acc[i][6].f.x) + bb[6];
            v1.w = (half ? acc[i][7].f.y : acc[i][7].f.x) + bb[7];
            *(float4*)(C + tx * 8)     = v0;
            *(float4*)(C + tx * 8 + 4) = v1;
        }
    }
}

// ---------------------------------------------------------------------------
// Phase 2: ONE persistent kernel, software grid barrier between timesteps.
// 128 blocks x 512 threads (16 warps, 4/SMSP). Block b owns 4 hidden units
// (m0 = b*4), i.e. 16 gate columns g*512 + m0 + u.
// Whs2 [512 x 16] duplicated pairs: 64 KB (loaded once, lives whole kernel).
// Hs   [512 x 68] swizzled h staging: 136 KB. Reduction buffer Ap ALIASES Hs.
// Per step: coalesced stage h -> Hs (xor-4 col swizzle, conflict-free STS),
// 16-way split-K f32x2 GEMM (32 k per warp), reduce via Ap, gates; c in reg.
// ---------------------------------------------------------------------------
#define HS_STRIDE 68

__global__ __launch_bounds__(NTHR) void lstm_persist_kernel(
    const float* __restrict__ Wh,     // [512, 2048]
    const float* __restrict__ h0,     // [64, 512]
    float* __restrict__ out)          // [64, 1024, 512]
{
    extern __shared__ char sm_raw[];
    float2* Whs2 = (float2*)sm_raw;                       // [512*16] pairs, 64KB
    float*  Hs   = (float*)(sm_raw + 65536);              // [512][68], 136KB
    float*  Ap   = Hs;                                    // aliased reduce buf

    const int tid  = threadIdx.x;
    const int w    = tid >> 5;
    const int lane = tid & 31;
    const int ln   = lane >> 2;   // 0..7  -> n group (8 batches)
    const int lc   = lane & 3;    // 0..3  -> c group (4 cols)
    const int m0   = blockIdx.x * 4;

    // Load Wh slice once, duplicated: col c = g*4+u -> global g*512 + m0 + u
    {
        const int wc  = tid & 15;
        const int wk0 = tid >> 4;       // 0..31
        const int wcol = (wc >> 2) * HH + m0 + (wc & 3);
        #pragma unroll 4
        for (int j = 0; j < 16; ++j) {
            int k = wk0 + 32 * j;
            float v = Wh[(size_t)k * FH + wcol];
            Whs2[k * 16 + wc] = make_float2(v, v);
        }
    }

    const int en = (tid >> 2) & 63;   // epilogue batch 0..63 (tid<256 active)
    const int eu = tid & 3;           // epilogue unit  0..3
    float creg = 0.f;

    // Staging map: 8 threads per batch row, lanes span columns (coalesced).
    const int hn = tid >> 3;      // batch row 0..63
    const int hq = tid & 7;       // column-quad phase 0..7
    const int hcol = hn ^ (4 * hq);   // swizzled Hs column (conflict-free STS)

    for (int t = 0; t < TT; ++t) {
        // Prefetch xw for this step (contiguous [t] slab; independent of barrier)
        float xwv[4];
        #pragma unroll
        for (int g = 0; g < 4; ++g)
            xwv[g] = g_xw[(size_t)(t * NB + en) * FH + g * HH + m0 + eu];

        const float* hp = (t == 0) ? h0 : g_h[(t - 1) & 1];

        if (t > 0) {
            __threadfence();          // release own h stores
            __syncthreads();
            if (tid == 0) {
                atomicAdd(&g_bar, 1u);
                const unsigned target = (unsigned)t * GRID_R;
                while (*((volatile unsigned*)&g_bar) < target) { }
                __threadfence();      // acquire
            }
            __syncthreads();
        }

        // Stage h_{t-1} -> Hs transposed+swizzled.
        // Thread (hn, hq) loads float4 q = hq + 8j of row hn (coalesced:
        // warp = 4 rows x 8 consecutive float4 = 4 x 128B segments).
        {
            const float4* hrow = (const float4*)(hp + (size_t)hn * HH);
            #pragma unroll 4
            for (int j = 0; j < 16; ++j) {
                int q = hq + 8 * j;                 // float4 index 0..127
                float4 v = __ldcg(hrow + q);
                // rows r = q*4 + i; swizzle s(r) = 4*((r>>2)&7) = 4*hq (const)
                Hs[(q * 4 + 0) * HS_STRIDE + hcol] = v.x;
                Hs[(q * 4 + 1) * HS_STRIDE + hcol] = v.y;
                Hs[(q * 4 + 2) * HS_STRIDE + hcol] = v.z;
                Hs[(q * 4 + 3) * HS_STRIDE + hcol] = v.w;
            }
        }
        __syncthreads();

        // Split-K: warp w owns k in [w*32, w*32+32). Lane tile 8n x 4c,
        // n packed into 4 f32x2 pairs; Wh operand pre-duplicated pairs.
        F2 acc[4][4];
        #pragma unroll
        for (int p = 0; p < 4; ++p)
            #pragma unroll
            for (int j = 0; j < 4; ++j)
                acc[p][j].u = 0ull;

        #pragma unroll 4
        for (int kk = 0; kk < 32; ++kk) {
            int k = w * 32 + kk;
            int s = 4 * ((k >> 2) & 7);             // column swizzle for row k
            const float* hrow = &Hs[k * HS_STRIDE];
            float4 ha = *(const float4*)&hrow[(ln * 8) ^ s];
            float4 hb = *(const float4*)&hrow[(ln * 8 + 4) ^ s];
            F2 hv[4];
            hv[0].f = make_float2(ha.x, ha.y);
            hv[1].f = make_float2(ha.z, ha.w);
            hv[2].f = make_float2(hb.x, hb.y);
            hv[3].f = make_float2(hb.z, hb.w);
            const float4* wp = (const float4*)&Whs2[k * 16 + lc * 4];
            float4 w0 = wp[0];                      // (c0,c0,c1,c1)
            float4 w1 = wp[1];                      // (c2,c2,c3,c3)
            F2 wv[4];
            wv[0].f = make_float2(w0.x, w0.y);
            wv[1].f = make_float2(w0.z, w0.w);
            wv[2].f = make_float2(w1.x, w1.y);
            wv[3].f = make_float2(w1.z, w1.w);
            #pragma unroll
            for (int j = 0; j < 4; ++j)
                #pragma unroll
                for (int p = 0; p < 4; ++p)
                    FMA2(acc[p][j], hv[p], wv[j]);
        }

        __syncthreads();   // all warps done READING Hs; safe to alias as Ap

        // Cross-warp reduce via padded smem (stride 66, float2 stores)
        #pragma unroll
        for (int p = 0; p < 4; ++p)
            #pragma unroll
            for (int j = 0; j < 4; ++j)
                *(float2*)&Ap[(w * 16 + lc * 4 + j) * 66 + ln * 8 + 2 * p] =
                    acc[p][j].f;
        __syncthreads();

        if (tid < 256) {
            float a[4];
            #pragma unroll
            for (int g = 0; g < 4; ++g) {
                float s = xwv[g];
                #pragma unroll
                for (int ww = 0; ww < 16; ++ww)
                    s += Ap[(ww * 16 + g * 4 + eu) * 66 + en];
                a[g] = s;
            }
            float ig = sigmoid_fast(a[0]);
            float fg = sigmoid_fast(a[1]);
            float og = sigmoid_fast(a[2]);
            float gg = tanh_fast(a[3]);
            creg = fmaf(fg, creg, ig * gg);
            float hval = og * tanh_fast(creg);
            out[(size_t)en * TT * HH + (size_t)t * HH + m0 + eu] = hval;
            g_h[t & 1][en * HH + m0 + eu] = hval;
        }
    }
}

// ---------------------------------------------------------------------------
extern "C" void kernel_launch(void* const* d_in, const int* in_sizes, int n_in,
                              void* d_out, int out_size)
{
    const float* x  = (const float*)d_in[0];   // [64, 1024, 512]
    const float* h0 = (const float*)d_in[1];   // [64, 512]
    const float* Wx = (const float*)d_in[2];   // [512, 2048]
    const float* Wh = (const float*)d_in[3];   // [512, 2048]
    const float* b  = (const float*)d_in[4];   // [2048]
    float* out = (float*)d_out;                // [64, 1024, 512]

    const int smem_bytes = 65536 + DD * HS_STRIDE * 4;   // 64KB + 136KB = 200KB
    cudaFuncSetAttribute(lstm_persist_kernel,
                         cudaFuncAttributeMaxDynamicSharedMemorySize, smem_bytes);

    dim3 g1(FH / 128, (NB * TT) / 128);        // (16, 512)
    sgemm_xw_kernel<<<g1, 256>>>(x, Wx, b);

    lstm_persist_kernel<<<GRID_R, NTHR, smem_bytes>>>(Wh, h0, out);
}